// round 15
// baseline (speedup 1.0000x reference)
#include <cuda_runtime.h>
#include <cuda_fp16.h>
#include <math.h>

#define TLEN 4161
#define TPAD 4224
#define NC 33
#define DM 768
#define HH 24
#define DIN 1536
#define CVD 1664
#define DPJ 3224

#define ALPHA (1.0f/1024.0f)   // fp16 path: activations x16, weights x64
#define WSCALE 262144.0f       // int8 conv path weight scale (2^18)
#define AQMAX 32000.0f         // int8 conv path activation target (16-bit)

static __device__ float g_x  [TLEN*DM];
static __device__ float g_x2 [TLEN*DM];
static __device__ float g_mam[TLEN*DM];
static __device__ float g_zx [(size_t)TLEN*DPJ];
static __device__ float g_xBC[(size_t)TPAD*CVD];
static __device__ float g_dt [TPAD*HH];
static __device__ float g_acs[NC*HH*128];
static __device__ float g_ct [NC*HH];
static __device__ float g_G  [NC*128*128];
static __device__ float g_st [NC*HH*4096];
static __device__ float g_se [NC*HH*4096];
static __device__ float g_y  [(size_t)TLEN*DIN];
static __device__ float g_img[4096*DM];
static __device__ float g_e8 [64*DM];
static __device__ float g_sq [12288];
static __device__ float g_part[(size_t)3*4096*768 + 130*768];
static __device__ unsigned g_pA[(size_t)TLEN*DIN];       // packed fp16-split activations
static __device__ unsigned g_pB[(size_t)DPJ*DM];         // packed fp16-split weights (projections)
static __device__ signed char g_qAh[(size_t)4096*768];   // int8 conv activations hi
static __device__ signed char g_qAl[(size_t)4096*768];   // int8 conv activations lo
static __device__ signed char g_qBh[(size_t)768*19200];  // int8 conv weights hi (transposed, k-perm)
static __device__ signed char g_qBl[(size_t)768*19200];  // int8 conv weights lo
static __device__ float g_inva[4096];                    // per-row max (staging)
static __device__ float g_gs[2];                         // [0]=quant scale, [1]=output inv scale

__device__ __forceinline__ float siluf(float x){ return x/(1.0f+expf(-x)); }

// ---------------- fp16-split helpers ----------------
__device__ __forceinline__ unsigned packh(float x){
    __half h = __float2half_rn(x);
    float r = x - __half2float(h);
    __half l = __float2half_rn(r);
    return ((unsigned)__half_as_ushort(l)<<16) | (unsigned)__half_as_ushort(h);
}
__device__ __forceinline__ unsigned prmt(unsigned a, unsigned b, unsigned s){
    unsigned r; asm("prmt.b32 %0,%1,%2,%3;" : "=r"(r) : "r"(a), "r"(b), "r"(s)); return r;
}
__device__ __forceinline__ void mmah(float* d, const unsigned* a, const unsigned* b){
    asm volatile("mma.sync.aligned.m16n8k16.row.col.f32.f16.f16.f32 "
        "{%0,%1,%2,%3}, {%4,%5,%6,%7}, {%8,%9}, {%0,%1,%2,%3};\n"
        : "+f"(d[0]),"+f"(d[1]),"+f"(d[2]),"+f"(d[3])
        : "r"(a[0]),"r"(a[1]),"r"(a[2]),"r"(a[3]), "r"(b[0]),"r"(b[1]));
}
__device__ __forceinline__ void immaq(int* d, const unsigned* a, const unsigned* b){
    asm volatile("mma.sync.aligned.m16n8k32.row.col.s32.s8.s8.s32 "
        "{%0,%1,%2,%3}, {%4,%5,%6,%7}, {%8,%9}, {%0,%1,%2,%3};\n"
        : "+r"(d[0]),"+r"(d[1]),"+r"(d[2]),"+r"(d[3])
        : "r"(a[0]),"r"(a[1]),"r"(a[2]),"r"(a[3]), "r"(b[0]),"r"(b[1]));
}
__device__ __forceinline__ void cp16(void* s, const void* g){
    unsigned sa = (unsigned)__cvta_generic_to_shared(s);
    asm volatile("cp.async.cg.shared.global [%0], [%1], 16;\n" :: "r"(sa), "l"(g));
}
__device__ __forceinline__ void cp16z(void* s, const void* g, bool v){
    unsigned sa = (unsigned)__cvta_generic_to_shared(s);
    int sz = v ? 16 : 0;
    asm volatile("cp.async.cg.shared.global [%0], [%1], 16, %2;\n" :: "r"(sa), "l"(g), "r"(sz));
}
#define CP_COMMIT() asm volatile("cp.async.commit_group;\n")
#define CP_WAIT1()  asm volatile("cp.async.wait_group 1;\n")
#define CP_WAIT0()  asm volatile("cp.async.wait_group 0;\n")

// k-permutation within a 32-group for IMMA k32 fragments:
// physical p = 8*((kk>>2)&3) + 4*(kk>>4) + (kk&3)
__device__ __forceinline__ int kperm(int kk){
    return ((kk&12)<<1) | ((kk&16)>>2) | (kk&3);
}

// ---------- weight pack (fp16 path): dst = pack(src * 64) ----------
__global__ void k_packw(const float* __restrict__ src, unsigned* __restrict__ dst, int n){
    int i = blockIdx.x*256 + threadIdx.x;
    if (i < n) dst[i] = packh(src[i]*64.0f);
}

// ---------- conv weight quantize (16-bit split) + transpose ----------
__global__ void k_packwq(const float* __restrict__ src){
    __shared__ float tl[32][33];
    int k0 = blockIdx.x*32, n0 = blockIdx.y*32;
    int tx = threadIdx.x, ty = threadIdx.y;
    #pragma unroll
    for (int j=0;j<4;j++)
        tl[ty+8*j][tx] = src[(size_t)(k0+ty+8*j)*768 + n0 + tx];
    __syncthreads();
    #pragma unroll
    for (int j=0;j<4;j++){
        int n = n0 + ty + 8*j, kk = tx;
        int q = __float2int_rn(tl[tx][ty+8*j]*WSCALE);
        q = max(-32000, min(32000, q));
        int hh = (q+128)>>8;
        int ll = q - (hh<<8);
        size_t idx = (size_t)n*19200 + k0 + kperm(kk);
        g_qBh[idx] = (signed char)hh;
        g_qBl[idx] = (signed char)ll;
    }
}

// ---------- build embeddings ----------
__global__ void k_e8(const float* __restrict__ im8, const float* __restrict__ w, const float* __restrict__ b){
    int i = blockIdx.x*256 + threadIdx.x;
    if (i >= 64*DM) return;
    int r = i/DM, d = i%DM;
    g_e8[i] = im8[r*3+0]*w[d*3+0] + im8[r*3+1]*w[d*3+1] + im8[r*3+2]*w[d*3+2] + b[d];
}
__global__ void k_buildx(const float* __restrict__ s0, const float* __restrict__ suffix){
    int i = blockIdx.x*256 + threadIdx.x;
    if (i >= TLEN*DM) return;
    int t = i/DM, d = i%DM;
    float v;
    if (t == 0) v = s0[d];
    else if (t <= 64) v = g_e8[(t-1)*DM + d];
    else {
        int p = t-65, py = p>>6, px = p&63;
        int blk = (py>>3)*8 + (px>>3);
        v = g_e8[blk*DM + d] + suffix[(size_t)p*DM + d];
    }
    g_x2[i] = v;
}

// ---------- layer norm -> fp32 out ----------
__global__ void k_ln(const float* __restrict__ in, float* __restrict__ out,
                     const float* __restrict__ w, const float* __restrict__ b){
    int t = blockIdx.x, tid = threadIdx.x;
    const float* x = in + (size_t)t*DM;
    float v0=x[tid], v1=x[tid+256], v2=x[tid+512];
    __shared__ float red[256];
    red[tid]=v0+v1+v2; __syncthreads();
    for (int o=128;o;o>>=1){ if(tid<o) red[tid]+=red[tid+o]; __syncthreads(); }
    float mu = red[0]*(1.0f/DM);
    __syncthreads();
    float d0=v0-mu, d1=v1-mu, d2=v2-mu;
    red[tid]=d0*d0+d1*d1+d2*d2; __syncthreads();
    for (int o=128;o;o>>=1){ if(tid<o) red[tid]+=red[tid+o]; __syncthreads(); }
    float r = rsqrtf(red[0]*(1.0f/DM) + 1e-5f);
    float* o = out + (size_t)t*DM;
    o[tid]=d0*r*w[tid]+b[tid]; o[tid+256]=d1*r*w[tid+256]+b[tid+256]; o[tid+512]=d2*r*w[tid+512]+b[tid+512];
}

// ---------- layer norm -> packed fp16-split (x16) out ----------
__global__ void k_ln_pack(const float* __restrict__ in, unsigned* __restrict__ out,
                          const float* __restrict__ w, const float* __restrict__ b){
    int t = blockIdx.x, tid = threadIdx.x;
    const float* x = in + (size_t)t*DM;
    float v0=x[tid], v1=x[tid+256], v2=x[tid+512];
    __shared__ float red[256];
    red[tid]=v0+v1+v2; __syncthreads();
    for (int o=128;o;o>>=1){ if(tid<o) red[tid]+=red[tid+o]; __syncthreads(); }
    float mu = red[0]*(1.0f/DM);
    __syncthreads();
    float d0=v0-mu, d1=v1-mu, d2=v2-mu;
    red[tid]=d0*d0+d1*d1+d2*d2; __syncthreads();
    for (int o=128;o;o>>=1){ if(tid<o) red[tid]+=red[tid+o]; __syncthreads(); }
    float r = rsqrtf(red[0]*(1.0f/DM) + 1e-5f);
    unsigned* o = out + (size_t)t*DM;
    o[tid]     = packh((d0*r*w[tid]     + b[tid])*16.0f);
    o[tid+256] = packh((d1*r*w[tid+256] + b[tid+256])*16.0f);
    o[tid+512] = packh((d2*r*w[tid+512] + b[tid+512])*16.0f);
}

// ---------- conv input LN: fp32 out to g_img + per-row max to g_inva ----------
__global__ void k_lnq(const float* __restrict__ in,
                      const float* __restrict__ w, const float* __restrict__ b){
    int t = blockIdx.x, tid = threadIdx.x;
    const float* x = in + (size_t)t*DM;
    float v0=x[tid], v1=x[tid+256], v2=x[tid+512];
    __shared__ float red[256];
    red[tid]=v0+v1+v2; __syncthreads();
    for (int o=128;o;o>>=1){ if(tid<o) red[tid]+=red[tid+o]; __syncthreads(); }
    float mu = red[0]*(1.0f/DM);
    __syncthreads();
    float d0=v0-mu, d1=v1-mu, d2=v2-mu;
    red[tid]=d0*d0+d1*d1+d2*d2; __syncthreads();
    for (int o=128;o;o>>=1){ if(tid<o) red[tid]+=red[tid+o]; __syncthreads(); }
    float r = rsqrtf(red[0]*(1.0f/DM) + 1e-5f);
    float y0 = d0*r*w[tid]+b[tid];
    float y1 = d1*r*w[tid+256]+b[tid+256];
    float y2 = d2*r*w[tid+512]+b[tid+512];
    float* o = &g_img[(size_t)t*DM];
    o[tid]=y0; o[tid+256]=y1; o[tid+512]=y2;
    __syncthreads();
    red[tid] = fmaxf(fmaxf(fabsf(y0),fabsf(y1)),fabsf(y2));
    __syncthreads();
    for (int o2=128;o2;o2>>=1){ if(tid<o2) red[tid]=fmaxf(red[tid],red[tid+o2]); __syncthreads(); }
    if (tid == 0) g_inva[t] = red[0];
}

// ---------- global scale from row maxes ----------
__global__ void k_gscale(){
    int tid = threadIdx.x;
    float m = 0.0f;
    for (int i=tid;i<4096;i+=256) m = fmaxf(m, g_inva[i]);
    __shared__ float red[256];
    red[tid]=m; __syncthreads();
    for (int o=128;o;o>>=1){ if(tid<o) red[tid]=fmaxf(red[tid],red[tid+o]); __syncthreads(); }
    if (tid==0){
        float mx = fmaxf(red[0], 1e-20f);
        g_gs[0] = AQMAX/mx;
        g_gs[1] = mx*(1.0f/(AQMAX*WSCALE));
    }
}

// ---------- quantize conv input with global scale (16-bit split, k-perm) ----------
__global__ void k_quant(){
    int t = blockIdx.x, tid = threadIdx.x;
    float sc = g_gs[0];
    const float* src = &g_img[(size_t)t*DM];
    #pragma unroll
    for (int j=0;j<3;j++){
        int k = tid + j*256;
        int q = __float2int_rn(src[k]*sc);
        q = max(-32000, min(32000, q));
        int hh = (q+128)>>8;
        int ll = q - (hh<<8);
        int idx = t*768 + (k&~31) + kperm(k&31);
        g_qAh[idx] = (signed char)hh;
        g_qAl[idx] = (signed char)ll;
    }
}

// ---------- SIMT NT sgemm (small batched G) ----------
__global__ void __launch_bounds__(256) k_gemm_nt(
    const float* __restrict__ A_, int lda, long long sA,
    const float* __restrict__ B_, int ldb, long long sB,
    float* __restrict__ C_, int ldc, long long sC,
    int M, int N, int K)
{
    const float* A = A_ + (size_t)blockIdx.z * sA;
    const float* B = B_ + (size_t)blockIdx.z * sB;
    float*       C = C_ + (size_t)blockIdx.z * sC;
    __shared__ float As[8][128];
    __shared__ float Bs[8][64];
    const int tid = threadIdx.x;
    const int m0 = blockIdx.y*128, n0 = blockIdx.x*64;
    const int alr = tid>>1, alc = (tid&1)*4;
    const int am = m0 + alr;
    const bool aok = am < M;
    const float* Ap = A + (size_t)(aok?am:0)*lda + alc;
    const int blr = tid>>1, blc = (tid&1)*4;
    const int bn = n0 + blr;
    const bool bld = tid < 128;
    const bool bok = bld && (bn < N);
    const float* Bp = B + (size_t)(bok?bn:0)*ldb + blc;
    const int row0 = (tid>>4)*8, col0 = (tid&15)*4;
    float acc[8][4];
    #pragma unroll
    for (int i=0;i<8;i++){
        #pragma unroll
        for (int j=0;j<4;j++) acc[i][j]=0.0f;
    }
    for (int k0=0;k0<K;k0+=8){
        float4 av = aok ? *(const float4*)(Ap+k0) : make_float4(0,0,0,0);
        float4 bv = bok ? *(const float4*)(Bp+k0) : make_float4(0,0,0,0);
        __syncthreads();
        As[alc+0][alr]=av.x; As[alc+1][alr]=av.y; As[alc+2][alr]=av.z; As[alc+3][alr]=av.w;
        if (bld){ Bs[blc+0][blr]=bv.x; Bs[blc+1][blr]=bv.y; Bs[blc+2][blr]=bv.z; Bs[blc+3][blr]=bv.w; }
        __syncthreads();
        #pragma unroll
        for (int kk=0;kk<8;kk++){
            float a[8], bb[4];
            *(float4*)&a[0] = *(const float4*)&As[kk][row0];
            *(float4*)&a[4] = *(const float4*)&As[kk][row0+4];
            *(float4*)&bb[0] = *(const float4*)&Bs[kk][col0];
            #pragma unroll
            for (int i=0;i<8;i++){
                #pragma unroll
                for (int j=0;j<4;j++) acc[i][j] = fmaf(a[i], bb[j], acc[i][j]);
            }
        }
    }
    #pragma unroll
    for (int i=0;i<8;i++){
        int m = m0+row0+i;
        if (m < M){
            #pragma unroll
            for (int j=0;j<4;j++){
                int n = n0+col0+j;
                if (n < N) C[(size_t)m*ldc + n] = acc[i][j];
            }
        }
    }
}

// ---------- fp16-split NT GEMM (3-product, proven R5): C = ALPHA * A * B^T ----------
__global__ void __launch_bounds__(256) k_mma_nt_h(
    const unsigned* __restrict__ A, int lda,
    const unsigned* __restrict__ B, int ldb,
    float* __restrict__ C, int ldc, long long csplit,
    int M, int N, int K, int kchunk)
{
    __shared__ __align__(16) unsigned As[2][128][20];
    __shared__ __align__(16) unsigned Bs[2][128][20];
    const int tid = threadIdx.x;
    const int m0 = blockIdx.y*128, n0 = blockIdx.x*128;
    const int kbeg = blockIdx.z * kchunk;
    const int kend = min(kbeg + kchunk, K);
    C += (long long)blockIdx.z * csplit;

    const int lrow = tid>>2;
    const int lk4  = (tid&3)*4;
    const int am0 = min(m0 + lrow, M-1), am1 = min(m0 + lrow + 64, M-1);
    const int bn0 = min(n0 + lrow, N-1), bn1 = min(n0 + lrow + 64, N-1);
    const unsigned* Ap0 = A + (size_t)am0*lda + lk4;
    const unsigned* Ap1 = A + (size_t)am1*lda + lk4;
    const unsigned* Bp0 = B + (size_t)bn0*ldb + lk4;
    const unsigned* Bp1 = B + (size_t)bn1*ldb + lk4;

    const int lane = tid&31, warp = tid>>5;
    const int wm = warp>>2, wn = warp&3;
    const int g = lane>>2, tg = lane&3;

    float acc[4][4][4];
    #pragma unroll
    for (int a=0;a<4;a++)
        #pragma unroll
        for (int b=0;b<4;b++)
            #pragma unroll
            for (int c=0;c<4;c++) acc[a][b][c]=0.0f;

    const int nst = (kend - kbeg) / 16;

    {
        cp16(&As[0][lrow][lk4],    Ap0 + kbeg);
        cp16(&As[0][lrow+64][lk4], Ap1 + kbeg);
        cp16(&Bs[0][lrow][lk4],    Bp0 + kbeg);
        cp16(&Bs[0][lrow+64][lk4], Bp1 + kbeg);
        CP_COMMIT();
    }

    for (int s=0; s<nst; s++){
        const int buf = s&1;
        if (s+1 < nst){
            const int k0 = kbeg + (s+1)*16;
            cp16(&As[buf^1][lrow][lk4],    Ap0 + k0);
            cp16(&As[buf^1][lrow+64][lk4], Ap1 + k0);
            cp16(&Bs[buf^1][lrow][lk4],    Bp0 + k0);
            cp16(&Bs[buf^1][lrow+64][lk4], Bp1 + k0);
            CP_COMMIT();
            CP_WAIT1();
        } else {
            CP_WAIT0();
        }
        __syncthreads();
        unsigned ah[4][4], al[4][4], bh[4][2], bl[4][2];
        #pragma unroll
        for (int mt=0; mt<4; mt++){
            int r0 = wm*64 + mt*16 + g;
            unsigned long long q0 = *(const unsigned long long*)&As[buf][r0][2*tg];
            unsigned long long q1 = *(const unsigned long long*)&As[buf][r0+8][2*tg];
            unsigned long long q2 = *(const unsigned long long*)&As[buf][r0][2*tg+8];
            unsigned long long q3 = *(const unsigned long long*)&As[buf][r0+8][2*tg+8];
            ah[mt][0]=prmt((unsigned)q0,(unsigned)(q0>>32),0x5410u); al[mt][0]=prmt((unsigned)q0,(unsigned)(q0>>32),0x7632u);
            ah[mt][1]=prmt((unsigned)q1,(unsigned)(q1>>32),0x5410u); al[mt][1]=prmt((unsigned)q1,(unsigned)(q1>>32),0x7632u);
            ah[mt][2]=prmt((unsigned)q2,(unsigned)(q2>>32),0x5410u); al[mt][2]=prmt((unsigned)q2,(unsigned)(q2>>32),0x7632u);
            ah[mt][3]=prmt((unsigned)q3,(unsigned)(q3>>32),0x5410u); al[mt][3]=prmt((unsigned)q3,(unsigned)(q3>>32),0x7632u);
        }
        #pragma unroll
        for (int nt=0; nt<4; nt++){
            int r = wn*32 + nt*8 + g;
            unsigned long long p0 = *(const unsigned long long*)&Bs[buf][r][2*tg];
            unsigned long long p1 = *(const unsigned long long*)&Bs[buf][r][2*tg+8];
            bh[nt][0]=prmt((unsigned)p0,(unsigned)(p0>>32),0x5410u); bl[nt][0]=prmt((unsigned)p0,(unsigned)(p0>>32),0x7632u);
            bh[nt][1]=prmt((unsigned)p1,(unsigned)(p1>>32),0x5410u); bl[nt][1]=prmt((unsigned)p1,(unsigned)(p1>>32),0x7632u);
        }
        #pragma unroll
        for (int mt=0; mt<4; mt++)
            #pragma unroll
            for (int nt=0; nt<4; nt++){
                mmah(&acc[mt][nt][0], ah[mt], bh[nt]);
                mmah(&acc[mt][nt][0], ah[mt], bl[nt]);
                mmah(&acc[mt][nt][0], al[mt], bh[nt]);
            }
        __syncthreads();
    }

    #pragma unroll
    for (int mt=0; mt<4; mt++){
        #pragma unroll
        for (int nt=0; nt<4; nt++){
            int m = m0 + wm*64 + mt*16 + g;
            int n = n0 + wn*32 + nt*8 + 2*tg;
            if (n < N){
                if (m < M){
                    float2 v; v.x = acc[mt][nt][0]*ALPHA; v.y = acc[mt][nt][1]*ALPHA;
                    *(float2*)&C[(size_t)m*ldc + n] = v;
                }
                if (m+8 < M){
                    float2 v; v.x = acc[mt][nt][2]*ALPHA; v.y = acc[mt][nt][3]*ALPHA;
                    *(float2*)&C[(size_t)(m+8)*ldc + n] = v;
                }
            }
        }
    }
}

// ---------- int8 implicit-GEMM conv2d 5x5 (exact 16-bit split, 4 products, split-K=3) ----------
__global__ void __launch_bounds__(256) k_conv_q(){
    __shared__ __align__(16) signed char sAh[2][128][32];
    __shared__ __align__(16) signed char sAl[2][128][32];
    __shared__ __align__(16) signed char sBh[2][64][32];
    __shared__ __align__(16) signed char sBl[2][64][32];
    const int tid = threadIdx.x;
    const int n0 = blockIdx.x*64, m0 = blockIdx.y*128, z = blockIdx.z;
    const int kbeg = z*6400;

    const int ar = tid>>1, ac16 = (tid&1)*16;
    const int py = (m0+ar)>>6, px = (m0+ar)&63;
    const int bp = tid>>7, br = (tid&127)>>1, bc16 = (tid&1)*16;
    const signed char* Bsrc = bp ? g_qBl : g_qBh;

    const int lane = tid&31, warp = tid>>5;
    const int wm = warp>>2, wn = warp&3;
    const int g = lane>>2, tg = lane&3;

    int acch[4][2][4], accm[4][2][4], accl[4][2][4];
    #pragma unroll
    for (int a=0;a<4;a++)
        #pragma unroll
        for (int b=0;b<2;b++)
            #pragma unroll
            for (int c=0;c<4;c++){ acch[a][b][c]=0; accm[a][b][c]=0; accl[a][b][c]=0; }

    // prologue
    {
        const int k0 = kbeg;
        const int tap = k0/768, ci = k0 - tap*768;
        const int ky = tap/5 - 2, kx = tap - (tap/5)*5 - 2;
        int sy=py+ky, sx=px+kx; bool v = ((unsigned)sy<64u) && ((unsigned)sx<64u);
        int o = v ? ((sy<<6)+sx) : 0;
        size_t so = (size_t)o*768 + ci + ac16;
        cp16z(&sAh[0][ar][ac16], g_qAh + so, v);
        cp16z(&sAl[0][ar][ac16], g_qAl + so, v);
        signed char* bd = bp ? &sBl[0][br][bc16] : &sBh[0][br][bc16];
        cp16(bd, Bsrc + (size_t)(n0+br)*19200 + k0 + bc16);
        CP_COMMIT();
    }

    for (int s=0; s<200; s++){
        const int buf = s&1;
        if (s+1 < 200){
            const int k0 = kbeg + (s+1)*32;
            const int tap = k0/768, ci = k0 - tap*768;
            const int ky = tap/5 - 2, kx = tap - (tap/5)*5 - 2;
            int sy=py+ky, sx=px+kx; bool v = ((unsigned)sy<64u) && ((unsigned)sx<64u);
            int o = v ? ((sy<<6)+sx) : 0;
            size_t so = (size_t)o*768 + ci + ac16;
            cp16z(&sAh[buf^1][ar][ac16], g_qAh + so, v);
            cp16z(&sAl[buf^1][ar][ac16], g_qAl + so, v);
            signed char* bd = bp ? &sBl[buf^1][br][bc16] : &sBh[buf^1][br][bc16];
            cp16(bd, Bsrc + (size_t)(n0+br)*19200 + k0 + bc16);
            CP_COMMIT();
            CP_WAIT1();
        } else {
            CP_WAIT0();
        }
        __syncthreads();
        unsigned bhf[2][2], blf[2][2];
        #pragma unroll
        for (int nt=0; nt<2; nt++){
            int c = wn*16 + nt*8 + g;
            unsigned long long q = *(const unsigned long long*)&sBh[buf][c][8*tg];
            unsigned long long r = *(const unsigned long long*)&sBl[buf][c][8*tg];
            bhf[nt][0]=(unsigned)q; bhf[nt][1]=(unsigned)(q>>32);
            blf[nt][0]=(unsigned)r; blf[nt][1]=(unsigned)(r>>32);
        }
        #pragma unroll
        for (int mt=0; mt<4; mt++){
            int r0 = wm*64 + mt*16 + g;
            unsigned long long h0 = *(const unsigned long long*)&sAh[buf][r0][8*tg];
            unsigned long long h1 = *(const unsigned long long*)&sAh[buf][r0+8][8*tg];
            unsigned long long l0 = *(const unsigned long long*)&sAl[buf][r0][8*tg];
            unsigned long long l1 = *(const unsigned long long*)&sAl[buf][r0+8][8*tg];
            unsigned af[4] = {(unsigned)h0,(unsigned)h1,(unsigned)(h0>>32),(unsigned)(h1>>32)};
            unsigned lf[4] = {(unsigned)l0,(unsigned)l1,(unsigned)(l0>>32),(unsigned)(l1>>32)};
            #pragma unroll
            for (int nt=0; nt<2; nt++){
                immaq(&acch[mt][nt][0], af, bhf[nt]);
                immaq(&accm[mt][nt][0], af, blf[nt]);
                immaq(&accm[mt][nt][0], lf, bhf[nt]);
                immaq(&accl[mt][nt][0], lf, blf[nt]);
            }
        }
        __syncthreads();
    }

    float inv = g_gs[1];
    float* P = g_part + (size_t)z*4096*768;
    #pragma unroll
    for (int mt=0; mt<4; mt++){
        int m = m0 + wm*64 + mt*16 + g;
        #pragma unroll
        for (int nt=0; nt<2; nt++){
            int n = n0 + wn*16 + nt*8 + 2*tg;
            float2 v0;
            v0.x = (65536.0f*(float)acch[mt][nt][0] + 256.0f*(float)accm[mt][nt][0] + (float)accl[mt][nt][0]) * inv;
            v0.y = (65536.0f*(float)acch[mt][nt][1] + 256.0f*(float)accm[mt][nt][1] + (float)accl[mt][nt][1]) * inv;
            *(float2*)&P[(size_t)m*768 + n] = v0;
            float2 v1;
            v1.x = (65536.0f*(float)acch[mt][nt][2] + 256.0f*(float)accm[mt][nt][2] + (float)accl[mt][nt][2]) * inv;
            v1.y = (65536.0f*(float)acch[mt][nt][3] + 256.0f*(float)accm[mt][nt][3] + (float)accl[mt][nt][3]) * inv;
            *(float2*)&P[(size_t)(m+8)*768 + n] = v1;
        }
    }
}

// ---------- split-K reductions ----------
__global__ void k_red2(){
    int i = blockIdx.x*256 + threadIdx.x;
    if (i >= TLEN*DM) return;
    const size_t S = (size_t)TLEN*DM;
    g_mam[i] = g_part[i] + g_part[i+S];
}
__global__ void k_red3b(const float* __restrict__ bias){
    int i = blockIdx.x*256 + threadIdx.x;
    if (i >= 4096*768) return;
    const size_t S = (size_t)4096*768;
    g_img[i] = g_part[i] + g_part[i+S] + g_part[i+2*S] + bias[i%768];
}

// ---------- dt = softplus(raw + bias) ----------
__global__ void k_dt(const float* __restrict__ dtb){
    int i = blockIdx.x*256 + threadIdx.x;
    if (i >= TPAD*HH) return;
    int t = i/HH, h = i%HH;
    float v = 0.0f;
    if (t < TLEN){
        float x = g_zx[(size_t)t*DPJ + 3200 + h] + dtb[h];
        v = (x > 20.0f) ? x : log1pf(expf(x));
    }
    g_dt[i] = v;
}

// ---------- causal depthwise conv1d (k=4) + silu ----------
__global__ void k_conv1d(const float* __restrict__ cw, const float* __restrict__ cb){
    int c = blockIdx.x*256 + threadIdx.x;
    if (c >= CVD) return;
    int t = blockIdx.y;
    float v = 0.0f;
    if (t < TLEN){
        float s = cb[c];
        #pragma unroll
        for (int j=0;j<4;j++){
            int ts = t-3+j;
            if (ts >= 0) s += cw[c*4+j]*g_zx[(size_t)ts*DPJ + 1536 + c];
        }
        v = siluf(s);
    }
    g_xBC[(size_t)t*CVD + c] = v;
}

// ---------- per-(chunk,head) cumsum of a = dt * (-exp(A_log)) ----------
__global__ void k_chunkscan(const float* __restrict__ A_log){
    int bb = blockIdx.x, c = bb/HH, h = bb%HH, tid = threadIdx.x;
    float Ah = -expf(A_log[h]);
    float a = g_dt[(c*128+tid)*HH + h] * Ah;
    __shared__ float sh[128];
    sh[tid] = a; __syncthreads();
    for (int o=1;o<128;o<<=1){
        float v = (tid>=o) ? sh[tid-o] : 0.0f;
        __syncthreads();
        sh[tid] += v;
        __syncthreads();
    }
    g_acs[bb*128+tid] = sh[tid];
    if (tid == 127) g_ct[bb] = sh[tid];
}

// ---------- chunk states ----------
__global__ void __launch_bounds__(256) k_states(){
    int h = blockIdx.x, c = blockIdx.y, ch = c*HH+h, tid = threadIdx.x;
    __shared__ float Bw[64][64];
    __shared__ float Xs[64][64];
    __shared__ float wl[64], dl[64];
    float ctot = g_ct[ch];
    int n0 = (tid>>4)*4, p0 = (tid&15)*4;
    float acc[4][4];
    #pragma unroll
    for (int i=0;i<4;i++){
        #pragma unroll
        for (int j=0;j<4;j++) acc[i][j]=0.0f;
    }
    for (int l0=0;l0<128;l0+=64){
        __syncthreads();
        if (tid < 64){
            int t = c*128 + l0 + tid;
            wl[tid] = expf(ctot - g_acs[ch*128 + l0 + tid]);
            dl[tid] = g_dt[t*HH + h];
        }
        __syncthreads();
        for (int i=tid;i<64*64;i+=256){
            int l = i>>6, q = i&63;
            const float* row = &g_xBC[(size_t)(c*128+l0+l)*CVD];
            Bw[l][q] = row[1536+q]*wl[l];
            Xs[l][q] = row[h*64+q]*dl[l];
        }
        __syncthreads();
        for (int l=0;l<64;l++){
            float a[4], bb[4];
            *(float4*)&a[0]  = *(const float4*)&Bw[l][n0];
            *(float4*)&bb[0] = *(const float4*)&Xs[l][p0];
            #pragma unroll
            for (int i=0;i<4;i++){
                #pragma unroll
                for (int j=0;j<4;j++) acc[i][j] = fmaf(a[i], bb[j], acc[i][j]);
            }
        }
    }
    float* o = &g_st[(size_t)ch*4096];
    #pragma unroll
    for (int i=0;i<4;i++){
        #pragma unroll
        for (int j=0;j<4;j++) o[(n0+i)*64 + p0+j] = acc[i][j];
    }
}

// ---------- inter-chunk serial recurrence ----------
__global__ void k_state_scan(){
    int h = blockIdx.x, tid = threadIdx.x;
    float S[16];
    #pragma unroll
    for (int j=0;j<16;j++) S[j]=0.0f;
    for (int z=0;z<NC;z++){
        int ch = z*HH + h;
        float f = expf(g_ct[ch]);
        float* se = &g_se[(size_t)ch*4096];
        const float* st = &g_st[(size_t)ch*4096];
        #pragma unroll
        for (int j=0;j<16;j++){
            int idx = tid + j*256;
            se[idx] = S[j];
            S[j] = f*S[j] + st[idx];
        }
    }
}

// ---------- Y = Yd + Yo + D*xh per (chunk,head) ----------
__global__ void __launch_bounds__(256) k_y(const float* __restrict__ A_log, const float* __restrict__ Dp){
    int h = blockIdx.x, c = blockIdx.y, ch = c*HH+h, tid = threadIdx.x;
    __shared__ float sA[128][33];
    __shared__ float sB[32][68];
    __shared__ float sAcs[128];
    __shared__ float sEap[128];
    int p0 = (tid&15)*4, l0 = (tid>>4)*8;
    if (tid < 128){
        sAcs[tid] = g_acs[ch*128+tid];
        float Ah = -expf(A_log[h]);
        sEap[tid] = expf(g_dt[(c*128+tid)*HH + h]*Ah);
    }
    __syncthreads();
    float acc[8][4];
    #pragma unroll
    for (int i=0;i<8;i++){
        #pragma unroll
        for (int j=0;j<4;j++) acc[i][j]=0.0f;
    }
    for (int n0=0;n0<64;n0+=32){
        __syncthreads();
        for (int i=tid;i<128*32;i+=256){
            int l=i>>5, nc=i&31;
            sA[l][nc] = g_xBC[(size_t)(c*128+l)*CVD + 1600 + n0 + nc];
        }
        for (int i=tid;i<32*64;i+=256){
            int nc=i>>6, p=i&63;
            sB[nc][p] = g_se[(size_t)ch*4096 + (n0+nc)*64 + p];
        }
        __syncthreads();
        for (int nc=0;nc<32;nc++){
            float bb[4];
            *(float4*)&bb[0] = *(const float4*)&sB[nc][p0];
            #pragma unroll
            for (int i=0;i<8;i++){
                float a = sA[l0+i][nc];
                #pragma unroll
                for (int j=0;j<4;j++) acc[i][j] = fmaf(a, bb[j], acc[i][j]);
            }
        }
    }
    #pragma unroll
    for (int i=0;i<8;i++){
        float e = expf(sAcs[l0+i]);
        #pragma unroll
        for (int j=0;j<4;j++) acc[i][j] *= e;
    }
    float m[8];
    #pragma unroll
    for (int i=0;i<8;i++) m[i]=0.0f;
    for (int s0=96;s0>=0;s0-=32){
        __syncthreads();
        for (int i=tid;i<128*32;i+=256){
            int l=i>>5, sc=i&31;
            sA[l][sc] = g_G[(size_t)c*16384 + l*128 + s0 + sc];
        }
        for (int i=tid;i<32*64;i+=256){
            int sc=i>>6, p=i&63;
            int t = c*128 + s0 + sc;
            sB[sc][p] = g_xBC[(size_t)t*CVD + h*64 + p]*g_dt[t*HH + h];
        }
        __syncthreads();
        if (l0+7 >= s0){
            for (int sc=31;sc>=0;sc--){
                int s = s0+sc;
                float es = sEap[(s+1)&127];
                float bb[4];
                *(float4*)&bb[0] = *(const float4*)&sB[sc][p0];
                #pragma unroll
                for (int i=0;i<8;i++){
                    int l = l0+i;
                    m[i] = (l==s) ? 1.0f : m[i]*es;
                    float co = (l>=s) ? sA[l][sc]*m[i] : 0.0f;
                    #pragma unroll
                    for (int j=0;j<4;j++) acc[i][j] = fmaf(co, bb[j], acc[i][j]);
                }
            }
        }
    }
    float Dph = Dp[h];
    #pragma unroll
    for (int i=0;i<8;i++){
        int t = c*128 + l0 + i;
        if (t < TLEN){
            #pragma unroll
            for (int j=0;j<4;j++){
                float xh = g_xBC[(size_t)t*CVD + h*64 + p0 + j];
                g_y[(size_t)t*DIN + h*64 + p0 + j] = acc[i][j] + Dph*xh;
            }
        }
    }
}

// ---------- y = y*silu(z); rmsnorm * rms_w; pack (x16) ----------
__global__ void k_gaterms(const float* __restrict__ rmsw, unsigned* __restrict__ packout){
    int t = blockIdx.x, tid = threadIdx.x;
    const float* z = &g_zx[(size_t)t*DPJ];
    const float* y = &g_y[(size_t)t*DIN];
    float v[6]; float ss=0.0f;
    #pragma unroll
    for (int j=0;j<6;j++){
        int k = tid + j*256;
        float g = z[k];
        float val = y[k]*siluf(g);
        v[j]=val; ss += val*val;
    }
    __shared__ float red[256];
    red[tid]=ss; __syncthreads();
    for (int o=128;o;o>>=1){ if(tid<o) red[tid]+=red[tid+o]; __syncthreads(); }
    float r = rsqrtf(red[0]*(1.0f/DIN) + 1e-5f);
    unsigned* po = packout + (size_t)t*DIN;
    #pragma unroll
    for (int j=0;j<6;j++){
        int k = tid + j*256;
        po[k] = packh(v[j]*r*rmsw[k]*16.0f);
    }
}

// ---------- residual + image flip ----------
__global__ void k_resid(const float* __restrict__ cur, float* __restrict__ nxt){
    int i = blockIdx.x*256 + threadIdx.x;
    if (i >= TLEN*DM) return;
    int t = i/DM, d = i%DM;
    float hv; int td;
    if (t < 65){ hv = g_mam[i]; td = t; }
    else { int p = t-65; hv = g_img[(size_t)p*DM + d]; td = 65 + (4095-p); }
    nxt[(size_t)td*DM + d] = cur[i] + hv;
}

// ---------- final projection + squared errors ----------
__global__ void k_yhat(const float* __restrict__ x, const float* __restrict__ w,
                       const float* __restrict__ b, const float* __restrict__ im64,
                       float* __restrict__ out, int out_size){
    int p = blockIdx.x;
    int ch = threadIdx.x>>5, lane = threadIdx.x&31;
    const float* xr = x + (size_t)(65+p)*DM;
    float s = 0.0f;
    for (int k=lane;k<DM;k+=32) s += xr[k]*w[ch*DM+k];
    for (int o=16;o;o>>=1) s += __shfl_down_sync(0xffffffffu, s, o);
    if (lane == 0){
        float yh = s + b[ch];
        int idx = p*3 + ch;
        int cap = out_size - (out_size&1);
        if (idx < cap) out[idx] = yh;
        float d = yh - im64[idx];
        g_sq[idx] = d*d;
    }
}
__global__ void k_loss(float* __restrict__ out, int out_size){
    int tid = threadIdx.x;
    float s = 0.0f;
    for (int i=tid;i<12288;i+=256) s += g_sq[i];
    __shared__ float red[256];
    red[tid]=s; __syncthreads();
    for (int o=128;o;o>>=1){ if(tid<o) red[tid]+=red[tid+o]; __syncthreads(); }
    if (tid==0 && (out_size&1)) out[out_size-1] = red[0]*(1.0f/12288.0f);
}

extern "C" void kernel_launch(void* const* d_in, const int* in_sizes, int n_in,
                              void* d_out, int out_size){
    const float* im8       = (const float*)d_in[0];
    const float* im64      = (const float*)d_in[1];
    const float* from_rgbw = (const float*)d_in[2];
    const float* from_rgbb = (const float*)d_in[3];
    const float* to_rgbw   = (const float*)d_in[4];
    const float* to_rgbb   = (const float*)d_in[5];
    const float* s0        = (const float*)d_in[6];
    const float* suffix    = (const float*)d_in[7];
    const float* norm0w    = (const float*)d_in[8];
    const float* norm0b    = (const float*)d_in[9];
    const float* in_projw  = (const float*)d_in[10];
    const float* conv1dw   = (const float*)d_in[11];
    const float* conv1db   = (const float*)d_in[12];
    const float* dt_bias   = (const float*)d_in[13];
    const float* A_log     = (const float*)d_in[14];
    const float* Dp        = (const float*)d_in[15];
    const float* rms_w     = (const float*)d_in[16];
    const float* out_projw = (const float*)d_in[17];
    const float* ln_w      = (const float*)d_in[18];
    const float* ln_b      = (const float*)d_in[19];
    const float* lnc_w     = (const float*)d_in[20];
    const float* lnc_b     = (const float*)d_in[21];
    const float* conv2dw   = (const float*)d_in[22];
    const float* conv2db   = (const float*)d_in[23];

    float *px, *px2, *pmam, *pzx, *pxbc, *pG, *ppart;
    unsigned *ppA, *ppB;
    cudaGetSymbolAddress((void**)&px,   g_x);
    cudaGetSymbolAddress((void**)&px2,  g_x2);
    cudaGetSymbolAddress((void**)&pmam, g_mam);
    cudaGetSymbolAddress((void**)&pzx,  g_zx);
    cudaGetSymbolAddress((void**)&pxbc, g_xBC);
    cudaGetSymbolAddress((void**)&pG,   g_G);
    cudaGetSymbolAddress((void**)&ppart,g_part);
    cudaGetSymbolAddress((void**)&ppA,  g_pA);
    cudaGetSymbolAddress((void**)&ppB,  g_pB);

    const int NB = (TLEN*DM + 255)/256;

    k_e8<<<(64*DM+255)/256, 256>>>(im8, from_rgbw, from_rgbb);
    k_buildx<<<NB, 256>>>(s0, suffix);
    k_ln<<<TLEN, 256>>>(px2, px, norm0w, norm0b);

    float* cur = px; float* nxt = px2;
    for (int i=0;i<8;i++){
        k_ln_pack<<<TLEN, 256>>>(cur, ppA, ln_w + i*DM, ln_b + i*DM);
        k_packw<<<(DPJ*DM+255)/256, 256>>>(in_projw + (size_t)i*DPJ*DM, ppB, DPJ*DM);
        k_mma_nt_h<<<dim3(26,33,1), 256>>>(ppA, DM, ppB, DM,
                                           pzx, DPJ, 0LL, TLEN, DPJ, DM, DM);
        k_dt<<<(TPAD*HH+255)/256, 256>>>(dt_bias + i*HH);
        k_conv1d<<<dim3(7, TPAD), 256>>>(conv1dw + (size_t)i*CVD*4, conv1db + i*CVD);
        k_chunkscan<<<NC*HH, 128>>>(A_log + i*HH);
        k_gemm_nt<<<dim3(2,1,NC), 256>>>(pxbc + 1600, CVD, (long long)128*CVD,
                                         pxbc + 1536, CVD, (long long)128*CVD,
                                         pG, 128, 16384, 128, 128, 64);
        k_states<<<dim3(HH,NC), 256>>>();
        k_state_scan<<<HH, 256>>>();
        k_y<<<dim3(HH,NC), 256>>>(A_log + i*HH, Dp + i*HH);
        k_gaterms<<<TLEN, 256>>>(rms_w + (size_t)i*DIN, ppA);
        k_packw<<<(DM*DIN+255)/256, 256>>>(out_projw + (size_t)i*DM*DIN, ppB, DM*DIN);
        k_mma_nt_h<<<dim3(6,33,2), 256>>>(ppA, DIN, ppB, DIN,
                                          ppart, DM, (long long)TLEN*DM, TLEN, DM, DIN, 768);
        k_red2<<<NB, 256>>>();
        // conv2d: int8 exact 16-bit-split path with GLOBAL activation scale
        k_lnq<<<4096, 256>>>(pmam + (size_t)65*DM, lnc_w + i*DM, lnc_b + i*DM);
        k_gscale<<<1, 256>>>();
        k_quant<<<4096, 256>>>();
        k_packwq<<<dim3(600,24), dim3(32,8)>>>(conv2dw + (size_t)i*14745600);
        k_conv_q<<<dim3(12,32,3), 256>>>();
        k_red3b<<<(4096*768+255)/256, 256>>>(conv2db + i*DM);
        k_resid<<<NB, 256>>>(cur, nxt);
        float* tmp = cur; cur = nxt; nxt = tmp;
    }
    k_yhat<<<4096, 96>>>(cur, to_rgbw, to_rgbb, im64, (float*)d_out, out_size);
    k_loss<<<1, 256>>>((float*)d_out, out_size);
}

// round 16
// speedup vs baseline: 2.5017x; 2.5017x over previous
#include <cuda_runtime.h>
#include <cuda_fp16.h>
#include <math.h>

#define TLEN 4161
#define TPAD 4224
#define NC 33
#define DM 768
#define HH 24
#define DIN 1536
#define CVD 1664
#define DPJ 3224

#define ALPHA (1.0f/1024.0f)   // activations x16, weights x64

static __device__ float g_x  [TLEN*DM];
static __device__ float g_x2 [TLEN*DM];
static __device__ float g_mam[TLEN*DM];
static __device__ float g_zx [(size_t)TLEN*DPJ];
static __device__ float g_xBC[(size_t)TPAD*CVD];
static __device__ float g_dt [TPAD*HH];
static __device__ float g_acs[NC*HH*128];
static __device__ float g_ct [NC*HH];
static __device__ float g_G  [NC*128*128];
static __device__ float g_st [NC*HH*4096];
static __device__ float g_se [NC*HH*4096];
static __device__ float g_y  [(size_t)TLEN*DIN];
static __device__ float g_img[4096*DM];
static __device__ float g_e8 [64*DM];
static __device__ float g_sq [12288];
static __device__ float g_part[(size_t)3*4096*768 + 130*768];
static __device__ unsigned g_pA[(size_t)TLEN*DIN];      // packed activations (lo16|hi16)
static __device__ unsigned g_pB[(size_t)19200*768];     // packed weights

__device__ __forceinline__ float siluf(float x){ return x/(1.0f+expf(-x)); }

// ---------------- fp16-split helpers ----------------
__device__ __forceinline__ unsigned packh(float x){
    __half h = __float2half_rn(x);
    float r = x - __half2float(h);
    __half l = __float2half_rn(r);
    return ((unsigned)__half_as_ushort(l)<<16) | (unsigned)__half_as_ushort(h);
}
__device__ __forceinline__ unsigned prmt(unsigned a, unsigned b, unsigned s){
    unsigned r; asm("prmt.b32 %0,%1,%2,%3;" : "=r"(r) : "r"(a), "r"(b), "r"(s)); return r;
}
__device__ __forceinline__ void mmah(float* d, const unsigned* a, const unsigned* b){
    asm volatile("mma.sync.aligned.m16n8k16.row.col.f32.f16.f16.f32 "
        "{%0,%1,%2,%3}, {%4,%5,%6,%7}, {%8,%9}, {%0,%1,%2,%3};\n"
        : "+f"(d[0]),"+f"(d[1]),"+f"(d[2]),"+f"(d[3])
        : "r"(a[0]),"r"(a[1]),"r"(a[2]),"r"(a[3]), "r"(b[0]),"r"(b[1]));
}
__device__ __forceinline__ void cp16(void* s, const void* g){
    unsigned sa = (unsigned)__cvta_generic_to_shared(s);
    asm volatile("cp.async.cg.shared.global [%0], [%1], 16;\n" :: "r"(sa), "l"(g));
}
__device__ __forceinline__ void cp16z(void* s, const void* g, bool v){
    unsigned sa = (unsigned)__cvta_generic_to_shared(s);
    int sz = v ? 16 : 0;
    asm volatile("cp.async.cg.shared.global [%0], [%1], 16, %2;\n" :: "r"(sa), "l"(g), "r"(sz));
}
#define CP_COMMIT() asm volatile("cp.async.commit_group;\n")
#define CP_WAIT1()  asm volatile("cp.async.wait_group 1;\n")
#define CP_WAIT0()  asm volatile("cp.async.wait_group 0;\n")

// ---------- weight pack: dst = pack(src * 64) ----------
__global__ void k_packw(const float* __restrict__ src, unsigned* __restrict__ dst, int n){
    int i = blockIdx.x*256 + threadIdx.x;
    if (i < n) dst[i] = packh(src[i]*64.0f);
}

// ---------- build embeddings ----------
__global__ void k_e8(const float* __restrict__ im8, const float* __restrict__ w, const float* __restrict__ b){
    int i = blockIdx.x*256 + threadIdx.x;
    if (i >= 64*DM) return;
    int r = i/DM, d = i%DM;
    g_e8[i] = im8[r*3+0]*w[d*3+0] + im8[r*3+1]*w[d*3+1] + im8[r*3+2]*w[d*3+2] + b[d];
}
__global__ void k_buildx(const float* __restrict__ s0, const float* __restrict__ suffix){
    int i = blockIdx.x*256 + threadIdx.x;
    if (i >= TLEN*DM) return;
    int t = i/DM, d = i%DM;
    float v;
    if (t == 0) v = s0[d];
    else if (t <= 64) v = g_e8[(t-1)*DM + d];
    else {
        int p = t-65, py = p>>6, px = p&63;
        int blk = (py>>3)*8 + (px>>3);
        v = g_e8[blk*DM + d] + suffix[(size_t)p*DM + d];
    }
    g_x2[i] = v;
}

// ---------- layer norm -> fp32 out ----------
__global__ void k_ln(const float* __restrict__ in, float* __restrict__ out,
                     const float* __restrict__ w, const float* __restrict__ b){
    int t = blockIdx.x, tid = threadIdx.x;
    const float* x = in + (size_t)t*DM;
    float v0=x[tid], v1=x[tid+256], v2=x[tid+512];
    __shared__ float red[256];
    red[tid]=v0+v1+v2; __syncthreads();
    for (int o=128;o;o>>=1){ if(tid<o) red[tid]+=red[tid+o]; __syncthreads(); }
    float mu = red[0]*(1.0f/DM);
    __syncthreads();
    float d0=v0-mu, d1=v1-mu, d2=v2-mu;
    red[tid]=d0*d0+d1*d1+d2*d2; __syncthreads();
    for (int o=128;o;o>>=1){ if(tid<o) red[tid]+=red[tid+o]; __syncthreads(); }
    float r = rsqrtf(red[0]*(1.0f/DM) + 1e-5f);
    float* o = out + (size_t)t*DM;
    o[tid]=d0*r*w[tid]+b[tid]; o[tid+256]=d1*r*w[tid+256]+b[tid+256]; o[tid+512]=d2*r*w[tid+512]+b[tid+512];
}

// ---------- layer norm -> packed fp16-split (x16) out ----------
__global__ void k_ln_pack(const float* __restrict__ in, unsigned* __restrict__ out,
                          const float* __restrict__ w, const float* __restrict__ b){
    int t = blockIdx.x, tid = threadIdx.x;
    const float* x = in + (size_t)t*DM;
    float v0=x[tid], v1=x[tid+256], v2=x[tid+512];
    __shared__ float red[256];
    red[tid]=v0+v1+v2; __syncthreads();
    for (int o=128;o;o>>=1){ if(tid<o) red[tid]+=red[tid+o]; __syncthreads(); }
    float mu = red[0]*(1.0f/DM);
    __syncthreads();
    float d0=v0-mu, d1=v1-mu, d2=v2-mu;
    red[tid]=d0*d0+d1*d1+d2*d2; __syncthreads();
    for (int o=128;o;o>>=1){ if(tid<o) red[tid]+=red[tid+o]; __syncthreads(); }
    float r = rsqrtf(red[0]*(1.0f/DM) + 1e-5f);
    unsigned* o = out + (size_t)t*DM;
    o[tid]     = packh((d0*r*w[tid]     + b[tid])*16.0f);
    o[tid+256] = packh((d1*r*w[tid+256] + b[tid+256])*16.0f);
    o[tid+512] = packh((d2*r*w[tid+512] + b[tid+512])*16.0f);
}

// ---------- SIMT NT sgemm (small batched G) ----------
__global__ void __launch_bounds__(256) k_gemm_nt(
    const float* __restrict__ A_, int lda, long long sA,
    const float* __restrict__ B_, int ldb, long long sB,
    float* __restrict__ C_, int ldc, long long sC,
    int M, int N, int K)
{
    const float* A = A_ + (size_t)blockIdx.z * sA;
    const float* B = B_ + (size_t)blockIdx.z * sB;
    float*       C = C_ + (size_t)blockIdx.z * sC;
    __shared__ float As[8][128];
    __shared__ float Bs[8][64];
    const int tid = threadIdx.x;
    const int m0 = blockIdx.y*128, n0 = blockIdx.x*64;
    const int alr = tid>>1, alc = (tid&1)*4;
    const int am = m0 + alr;
    const bool aok = am < M;
    const float* Ap = A + (size_t)(aok?am:0)*lda + alc;
    const int blr = tid>>1, blc = (tid&1)*4;
    const int bn = n0 + blr;
    const bool bld = tid < 128;
    const bool bok = bld && (bn < N);
    const float* Bp = B + (size_t)(bok?bn:0)*ldb + blc;
    const int row0 = (tid>>4)*8, col0 = (tid&15)*4;
    float acc[8][4];
    #pragma unroll
    for (int i=0;i<8;i++){
        #pragma unroll
        for (int j=0;j<4;j++) acc[i][j]=0.0f;
    }
    for (int k0=0;k0<K;k0+=8){
        float4 av = aok ? *(const float4*)(Ap+k0) : make_float4(0,0,0,0);
        float4 bv = bok ? *(const float4*)(Bp+k0) : make_float4(0,0,0,0);
        __syncthreads();
        As[alc+0][alr]=av.x; As[alc+1][alr]=av.y; As[alc+2][alr]=av.z; As[alc+3][alr]=av.w;
        if (bld){ Bs[blc+0][blr]=bv.x; Bs[blc+1][blr]=bv.y; Bs[blc+2][blr]=bv.z; Bs[blc+3][blr]=bv.w; }
        __syncthreads();
        #pragma unroll
        for (int kk=0;kk<8;kk++){
            float a[8], bb[4];
            *(float4*)&a[0] = *(const float4*)&As[kk][row0];
            *(float4*)&a[4] = *(const float4*)&As[kk][row0+4];
            *(float4*)&bb[0] = *(const float4*)&Bs[kk][col0];
            #pragma unroll
            for (int i=0;i<8;i++){
                #pragma unroll
                for (int j=0;j<4;j++) acc[i][j] = fmaf(a[i], bb[j], acc[i][j]);
            }
        }
    }
    #pragma unroll
    for (int i=0;i<8;i++){
        int m = m0+row0+i;
        if (m < M){
            #pragma unroll
            for (int j=0;j<4;j++){
                int n = n0+col0+j;
                if (n < N) C[(size_t)m*ldc + n] = acc[i][j];
            }
        }
    }
}

// ---------- fp16-split NT GEMM (3-product): C = ALPHA * A[M,K] * B[N,K]^T ----------
__global__ void __launch_bounds__(256) k_mma_nt_h(
    const unsigned* __restrict__ A, int lda,
    const unsigned* __restrict__ B, int ldb,
    float* __restrict__ C, int ldc, long long csplit,
    int M, int N, int K, int kchunk)
{
    __shared__ __align__(16) unsigned As[2][128][20];
    __shared__ __align__(16) unsigned Bs[2][128][20];
    const int tid = threadIdx.x;
    const int m0 = blockIdx.y*128, n0 = blockIdx.x*128;
    const int kbeg = blockIdx.z * kchunk;
    const int kend = min(kbeg + kchunk, K);
    C += (long long)blockIdx.z * csplit;

    const int lrow = tid>>2;
    const int lk4  = (tid&3)*4;
    const int am0 = min(m0 + lrow, M-1), am1 = min(m0 + lrow + 64, M-1);
    const int bn0 = min(n0 + lrow, N-1), bn1 = min(n0 + lrow + 64, N-1);
    const unsigned* Ap0 = A + (size_t)am0*lda + lk4;
    const unsigned* Ap1 = A + (size_t)am1*lda + lk4;
    const unsigned* Bp0 = B + (size_t)bn0*ldb + lk4;
    const unsigned* Bp1 = B + (size_t)bn1*ldb + lk4;

    const int lane = tid&31, warp = tid>>5;
    const int wm = warp>>2, wn = warp&3;
    const int g = lane>>2, tg = lane&3;

    float acc[4][4][4];
    #pragma unroll
    for (int a=0;a<4;a++)
        #pragma unroll
        for (int b=0;b<4;b++)
            #pragma unroll
            for (int c=0;c<4;c++) acc[a][b][c]=0.0f;

    const int nst = (kend - kbeg) / 16;

    {
        cp16(&As[0][lrow][lk4],    Ap0 + kbeg);
        cp16(&As[0][lrow+64][lk4], Ap1 + kbeg);
        cp16(&Bs[0][lrow][lk4],    Bp0 + kbeg);
        cp16(&Bs[0][lrow+64][lk4], Bp1 + kbeg);
        CP_COMMIT();
    }

    for (int s=0; s<nst; s++){
        const int buf = s&1;
        if (s+1 < nst){
            const int k0 = kbeg + (s+1)*16;
            cp16(&As[buf^1][lrow][lk4],    Ap0 + k0);
            cp16(&As[buf^1][lrow+64][lk4], Ap1 + k0);
            cp16(&Bs[buf^1][lrow][lk4],    Bp0 + k0);
            cp16(&Bs[buf^1][lrow+64][lk4], Bp1 + k0);
            CP_COMMIT();
            CP_WAIT1();
        } else {
            CP_WAIT0();
        }
        __syncthreads();
        unsigned ah[4][4], al[4][4], bh[4][2], bl[4][2];
        #pragma unroll
        for (int mt=0; mt<4; mt++){
            int r0 = wm*64 + mt*16 + g;
            unsigned long long q0 = *(const unsigned long long*)&As[buf][r0][2*tg];
            unsigned long long q1 = *(const unsigned long long*)&As[buf][r0+8][2*tg];
            unsigned long long q2 = *(const unsigned long long*)&As[buf][r0][2*tg+8];
            unsigned long long q3 = *(const unsigned long long*)&As[buf][r0+8][2*tg+8];
            ah[mt][0]=prmt((unsigned)q0,(unsigned)(q0>>32),0x5410u); al[mt][0]=prmt((unsigned)q0,(unsigned)(q0>>32),0x7632u);
            ah[mt][1]=prmt((unsigned)q1,(unsigned)(q1>>32),0x5410u); al[mt][1]=prmt((unsigned)q1,(unsigned)(q1>>32),0x7632u);
            ah[mt][2]=prmt((unsigned)q2,(unsigned)(q2>>32),0x5410u); al[mt][2]=prmt((unsigned)q2,(unsigned)(q2>>32),0x7632u);
            ah[mt][3]=prmt((unsigned)q3,(unsigned)(q3>>32),0x5410u); al[mt][3]=prmt((unsigned)q3,(unsigned)(q3>>32),0x7632u);
        }
        #pragma unroll
        for (int nt=0; nt<4; nt++){
            int r = wn*32 + nt*8 + g;
            unsigned long long p0 = *(const unsigned long long*)&Bs[buf][r][2*tg];
            unsigned long long p1 = *(const unsigned long long*)&Bs[buf][r][2*tg+8];
            bh[nt][0]=prmt((unsigned)p0,(unsigned)(p0>>32),0x5410u); bl[nt][0]=prmt((unsigned)p0,(unsigned)(p0>>32),0x7632u);
            bh[nt][1]=prmt((unsigned)p1,(unsigned)(p1>>32),0x5410u); bl[nt][1]=prmt((unsigned)p1,(unsigned)(p1>>32),0x7632u);
        }
        #pragma unroll
        for (int mt=0; mt<4; mt++)
            #pragma unroll
            for (int nt=0; nt<4; nt++){
                mmah(&acc[mt][nt][0], ah[mt], bh[nt]);
                mmah(&acc[mt][nt][0], ah[mt], bl[nt]);
                mmah(&acc[mt][nt][0], al[mt], bh[nt]);
            }
        __syncthreads();
    }

    #pragma unroll
    for (int mt=0; mt<4; mt++){
        #pragma unroll
        for (int nt=0; nt<4; nt++){
            int m = m0 + wm*64 + mt*16 + g;
            int n = n0 + wn*32 + nt*8 + 2*tg;
            if (n < N){
                if (m < M){
                    float2 v; v.x = acc[mt][nt][0]*ALPHA; v.y = acc[mt][nt][1]*ALPHA;
                    *(float2*)&C[(size_t)m*ldc + n] = v;
                }
                if (m+8 < M){
                    float2 v; v.x = acc[mt][nt][2]*ALPHA; v.y = acc[mt][nt][3]*ALPHA;
                    *(float2*)&C[(size_t)(m+8)*ldc + n] = v;
                }
            }
        }
    }
}

// ---------- fp16-split implicit-GEMM conv2d 5x5 (3-product, split-K=3) ----------
__global__ void __launch_bounds__(256) k_conv2d_mma_h(const unsigned* __restrict__ W){
    __shared__ __align__(16) unsigned As[2][128][20];
    __shared__ __align__(16) unsigned Bs[2][16][132];
    const int tid = threadIdx.x;
    const int n0 = blockIdx.x*128;
    const int m0 = blockIdx.y*128;
    const int z  = blockIdx.z;
    const int sbeg = z*400;

    const int lrow = tid>>2;
    const int lk4  = (tid&3)*4;
    const int mr0 = m0 + lrow, mr1 = m0 + lrow + 64;
    const int py0 = mr0>>6, px0 = mr0&63;
    const int py1 = mr1>>6, px1 = mr1&63;
    const int bkr = tid>>5;
    const int bnc = (tid&31)*4;

    const int lane = tid&31, warp = tid>>5;
    const int wm = warp>>2, wn = warp&3;
    const int g = lane>>2, tg = lane&3;

    float acc[4][4][4];
    #pragma unroll
    for (int a=0;a<4;a++)
        #pragma unroll
        for (int b=0;b<4;b++)
            #pragma unroll
            for (int c=0;c<4;c++) acc[a][b][c]=0.0f;

    {
        const int k0 = sbeg*16;
        const int tap = k0/768, ci = k0 - tap*768;
        const int ky = tap/5 - 2, kx = tap - (tap/5)*5 - 2;
        int sy0=py0+ky, sx0=px0+kx; bool v0 = ((unsigned)sy0<64u) && ((unsigned)sx0<64u);
        int sy1=py1+ky, sx1=px1+kx; bool v1 = ((unsigned)sy1<64u) && ((unsigned)sx1<64u);
        int o0 = v0 ? ((sy0<<6)+sx0) : 0;
        int o1 = v1 ? ((sy1<<6)+sx1) : 0;
        cp16z(&As[0][lrow][lk4],    &g_pA[(size_t)o0*768 + ci + lk4], v0);
        cp16z(&As[0][lrow+64][lk4], &g_pA[(size_t)o1*768 + ci + lk4], v1);
        cp16(&Bs[0][bkr][bnc],   &W[(size_t)(k0+bkr)*768 + n0 + bnc]);
        cp16(&Bs[0][bkr+8][bnc], &W[(size_t)(k0+bkr+8)*768 + n0 + bnc]);
        CP_COMMIT();
    }

    for (int s=0; s<400; s++){
        const int buf = s&1;
        if (s+1 < 400){
            const int k0 = (sbeg+s+1)*16;
            const int tap = k0/768, ci = k0 - tap*768;
            const int ky = tap/5 - 2, kx = tap - (tap/5)*5 - 2;
            int sy0=py0+ky, sx0=px0+kx; bool v0 = ((unsigned)sy0<64u) && ((unsigned)sx0<64u);
            int sy1=py1+ky, sx1=px1+kx; bool v1 = ((unsigned)sy1<64u) && ((unsigned)sx1<64u);
            int o0 = v0 ? ((sy0<<6)+sx0) : 0;
            int o1 = v1 ? ((sy1<<6)+sx1) : 0;
            cp16z(&As[buf^1][lrow][lk4],    &g_pA[(size_t)o0*768 + ci + lk4], v0);
            cp16z(&As[buf^1][lrow+64][lk4], &g_pA[(size_t)o1*768 + ci + lk4], v1);
            cp16(&Bs[buf^1][bkr][bnc],   &W[(size_t)(k0+bkr)*768 + n0 + bnc]);
            cp16(&Bs[buf^1][bkr+8][bnc], &W[(size_t)(k0+bkr+8)*768 + n0 + bnc]);
            CP_COMMIT();
            CP_WAIT1();
        } else {
            CP_WAIT0();
        }
        __syncthreads();
        unsigned ah[4][4], al[4][4], bh[4][2], bl[4][2];
        #pragma unroll
        for (int mt=0; mt<4; mt++){
            int r0 = wm*64 + mt*16 + g;
            unsigned long long q0 = *(const unsigned long long*)&As[buf][r0][2*tg];
            unsigned long long q1 = *(const unsigned long long*)&As[buf][r0+8][2*tg];
            unsigned long long q2 = *(const unsigned long long*)&As[buf][r0][2*tg+8];
            unsigned long long q3 = *(const unsigned long long*)&As[buf][r0+8][2*tg+8];
            ah[mt][0]=prmt((unsigned)q0,(unsigned)(q0>>32),0x5410u); al[mt][0]=prmt((unsigned)q0,(unsigned)(q0>>32),0x7632u);
            ah[mt][1]=prmt((unsigned)q1,(unsigned)(q1>>32),0x5410u); al[mt][1]=prmt((unsigned)q1,(unsigned)(q1>>32),0x7632u);
            ah[mt][2]=prmt((unsigned)q2,(unsigned)(q2>>32),0x5410u); al[mt][2]=prmt((unsigned)q2,(unsigned)(q2>>32),0x7632u);
            ah[mt][3]=prmt((unsigned)q3,(unsigned)(q3>>32),0x5410u); al[mt][3]=prmt((unsigned)q3,(unsigned)(q3>>32),0x7632u);
        }
        #pragma unroll
        for (int nt=0; nt<4; nt++){
            int cn = wn*32 + nt*8 + g;
            unsigned p0 = Bs[buf][2*tg][cn],   p1 = Bs[buf][2*tg+1][cn];
            unsigned p2 = Bs[buf][2*tg+8][cn], p3 = Bs[buf][2*tg+9][cn];
            bh[nt][0]=prmt(p0,p1,0x5410u); bl[nt][0]=prmt(p0,p1,0x7632u);
            bh[nt][1]=prmt(p2,p3,0x5410u); bl[nt][1]=prmt(p2,p3,0x7632u);
        }
        #pragma unroll
        for (int mt=0; mt<4; mt++)
            #pragma unroll
            for (int nt=0; nt<4; nt++){
                mmah(&acc[mt][nt][0], ah[mt], bh[nt]);
                mmah(&acc[mt][nt][0], ah[mt], bl[nt]);
                mmah(&acc[mt][nt][0], al[mt], bh[nt]);
            }
        __syncthreads();
    }

    float* P = g_part + (size_t)z*4096*768;
    #pragma unroll
    for (int mt=0; mt<4; mt++){
        #pragma unroll
        for (int nt=0; nt<4; nt++){
            int m = m0 + wm*64 + mt*16 + g;
            int n = n0 + wn*32 + nt*8 + 2*tg;
            float2 v0; v0.x = acc[mt][nt][0]*ALPHA; v0.y = acc[mt][nt][1]*ALPHA;
            *(float2*)&P[(size_t)m*768 + n] = v0;
            float2 v1; v1.x = acc[mt][nt][2]*ALPHA; v1.y = acc[mt][nt][3]*ALPHA;
            *(float2*)&P[(size_t)(m+8)*768 + n] = v1;
        }
    }
}

// ---------- split-K reductions ----------
__global__ void k_red2(){
    int i = blockIdx.x*256 + threadIdx.x;
    if (i >= TLEN*DM) return;
    const size_t S = (size_t)TLEN*DM;
    g_mam[i] = g_part[i] + g_part[i+S];
}
__global__ void k_red3b(const float* __restrict__ bias){
    int i = blockIdx.x*256 + threadIdx.x;
    if (i >= 4096*768) return;
    const size_t S = (size_t)4096*768;
    g_img[i] = g_part[i] + g_part[i+S] + g_part[i+2*S] + bias[i%768];
}

// ---------- dt = softplus(raw + bias) ----------
__global__ void k_dt(const float* __restrict__ dtb){
    int i = blockIdx.x*256 + threadIdx.x;
    if (i >= TPAD*HH) return;
    int t = i/HH, h = i%HH;
    float v = 0.0f;
    if (t < TLEN){
        float x = g_zx[(size_t)t*DPJ + 3200 + h] + dtb[h];
        v = (x > 20.0f) ? x : log1pf(expf(x));
    }
    g_dt[i] = v;
}

// ---------- causal depthwise conv1d (k=4) + silu, tiled smem ----------
__global__ void __launch_bounds__(256) k_conv1d(const float* __restrict__ cw, const float* __restrict__ cb){
    __shared__ float s[67][128];
    const int c0 = blockIdx.x*128, t0 = blockIdx.y*64;
    const int tid = threadIdx.x;
    for (int i = tid; i < 67*128; i += 256){
        int r = i>>7, c = i&127;
        int t = t0 - 3 + r;
        float v = 0.0f;
        if (t >= 0 && t < TLEN) v = g_zx[(size_t)t*DPJ + 1536 + c0 + c];
        s[r][c] = v;
    }
    __syncthreads();
    for (int i = tid; i < 64*128; i += 256){
        int r = i>>7, c = i&127;
        int t = t0 + r;
        int ch = c0 + c;
        if (t < TLEN){
            float sum = cb[ch];
            #pragma unroll
            for (int j=0;j<4;j++) sum = fmaf(cw[ch*4+j], s[r+j][c], sum);
            g_xBC[(size_t)t*CVD + ch] = siluf(sum);
        } else if (t < TPAD){
            g_xBC[(size_t)t*CVD + ch] = 0.0f;
        }
    }
}

// ---------- per-(chunk,head) cumsum of a = dt * (-exp(A_log)) ----------
__global__ void k_chunkscan(const float* __restrict__ A_log){
    int bb = blockIdx.x, c = bb/HH, h = bb%HH, tid = threadIdx.x;
    float Ah = -expf(A_log[h]);
    float a = g_dt[(c*128+tid)*HH + h] * Ah;
    __shared__ float sh[128];
    sh[tid] = a; __syncthreads();
    for (int o=1;o<128;o<<=1){
        float v = (tid>=o) ? sh[tid-o] : 0.0f;
        __syncthreads();
        sh[tid] += v;
        __syncthreads();
    }
    g_acs[bb*128+tid] = sh[tid];
    if (tid == 127) g_ct[bb] = sh[tid];
}

// ---------- chunk states ----------
__global__ void __launch_bounds__(256) k_states(){
    int h = blockIdx.x, c = blockIdx.y, ch = c*HH+h, tid = threadIdx.x;
    __shared__ float Bw[64][64];
    __shared__ float Xs[64][64];
    __shared__ float wl[64], dl[64];
    float ctot = g_ct[ch];
    int n0 = (tid>>4)*4, p0 = (tid&15)*4;
    float acc[4][4];
    #pragma unroll
    for (int i=0;i<4;i++){
        #pragma unroll
        for (int j=0;j<4;j++) acc[i][j]=0.0f;
    }
    for (int l0=0;l0<128;l0+=64){
        __syncthreads();
        if (tid < 64){
            int t = c*128 + l0 + tid;
            wl[tid] = expf(ctot - g_acs[ch*128 + l0 + tid]);
            dl[tid] = g_dt[t*HH + h];
        }
        __syncthreads();
        for (int i=tid;i<64*64;i+=256){
            int l = i>>6, q = i&63;
            const float* row = &g_xBC[(size_t)(c*128+l0+l)*CVD];
            Bw[l][q] = row[1536+q]*wl[l];
            Xs[l][q] = row[h*64+q]*dl[l];
        }
        __syncthreads();
        for (int l=0;l<64;l++){
            float a[4], bb[4];
            *(float4*)&a[0]  = *(const float4*)&Bw[l][n0];
            *(float4*)&bb[0] = *(const float4*)&Xs[l][p0];
            #pragma unroll
            for (int i=0;i<4;i++){
                #pragma unroll
                for (int j=0;j<4;j++) acc[i][j] = fmaf(a[i], bb[j], acc[i][j]);
            }
        }
    }
    float* o = &g_st[(size_t)ch*4096];
    #pragma unroll
    for (int i=0;i<4;i++){
        #pragma unroll
        for (int j=0;j<4;j++) o[(n0+i)*64 + p0+j] = acc[i][j];
    }
}

// ---------- inter-chunk serial recurrence ----------
__global__ void k_state_scan(){
    int h = blockIdx.x, tid = threadIdx.x;
    float S[16];
    #pragma unroll
    for (int j=0;j<16;j++) S[j]=0.0f;
    for (int z=0;z<NC;z++){
        int ch = z*HH + h;
        float f = expf(g_ct[ch]);
        float* se = &g_se[(size_t)ch*4096];
        const float* st = &g_st[(size_t)ch*4096];
        #pragma unroll
        for (int j=0;j<16;j++){
            int idx = tid + j*256;
            se[idx] = S[j];
            S[j] = f*S[j] + st[idx];
        }
    }
}

// ---------- Y = Yd + Yo + D*xh per (chunk,head) ----------
__global__ void __launch_bounds__(256) k_y(const float* __restrict__ A_log, const float* __restrict__ Dp){
    int h = blockIdx.x, c = blockIdx.y, ch = c*HH+h, tid = threadIdx.x;
    __shared__ float sA[128][33];
    __shared__ float sB[32][68];
    __shared__ float sAcs[128];
    __shared__ float sEap[128];
    int p0 = (tid&15)*4, l0 = (tid>>4)*8;
    if (tid < 128){
        sAcs[tid] = g_acs[ch*128+tid];
        float Ah = -expf(A_log[h]);
        sEap[tid] = expf(g_dt[(c*128+tid)*HH + h]*Ah);
    }
    __syncthreads();
    float acc[8][4];
    #pragma unroll
    for (int i=0;i<8;i++){
        #pragma unroll
        for (int j=0;j<4;j++) acc[i][j]=0.0f;
    }
    for (int n0=0;n0<64;n0+=32){
        __syncthreads();
        for (int i=tid;i<128*32;i+=256){
            int l=i>>5, nc=i&31;
            sA[l][nc] = g_xBC[(size_t)(c*128+l)*CVD + 1600 + n0 + nc];
        }
        for (int i=tid;i<32*64;i+=256){
            int nc=i>>6, p=i&63;
            sB[nc][p] = g_se[(size_t)ch*4096 + (n0+nc)*64 + p];
        }
        __syncthreads();
        for (int nc=0;nc<32;nc++){
            float bb[4];
            *(float4*)&bb[0] = *(const float4*)&sB[nc][p0];
            #pragma unroll
            for (int i=0;i<8;i++){
                float a = sA[l0+i][nc];
                #pragma unroll
                for (int j=0;j<4;j++) acc[i][j] = fmaf(a, bb[j], acc[i][j]);
            }
        }
    }
    #pragma unroll
    for (int i=0;i<8;i++){
        float e = expf(sAcs[l0+i]);
        #pragma unroll
        for (int j=0;j<4;j++) acc[i][j] *= e;
    }
    float m[8];
    #pragma unroll
    for (int i=0;i<8;i++) m[i]=0.0f;
    for (int s0=96;s0>=0;s0-=32){
        __syncthreads();
        for (int i=tid;i<128*32;i+=256){
            int l=i>>5, sc=i&31;
            sA[l][sc] = g_G[(size_t)c*16384 + l*128 + s0 + sc];
        }
        for (int i=tid;i<32*64;i+=256){
            int sc=i>>6, p=i&63;
            int t = c*128 + s0 + sc;
            sB[sc][p] = g_xBC[(size_t)t*CVD + h*64 + p]*g_dt[t*HH + h];
        }
        __syncthreads();
        if (l0+7 >= s0){
            for (int sc=31;sc>=0;sc--){
                int s = s0+sc;
                float es = sEap[(s+1)&127];
                float bb[4];
                *(float4*)&bb[0] = *(const float4*)&sB[sc][p0];
                #pragma unroll
                for (int i=0;i<8;i++){
                    int l = l0+i;
                    m[i] = (l==s) ? 1.0f : m[i]*es;
                    float co = (l>=s) ? sA[l][sc]*m[i] : 0.0f;
                    #pragma unroll
                    for (int j=0;j<4;j++) acc[i][j] = fmaf(co, bb[j], acc[i][j]);
                }
            }
        }
    }
    float Dph = Dp[h];
    #pragma unroll
    for (int i=0;i<8;i++){
        int t = c*128 + l0 + i;
        if (t < TLEN){
            #pragma unroll
            for (int j=0;j<4;j++){
                float xh = g_xBC[(size_t)t*CVD + h*64 + p0 + j];
                g_y[(size_t)t*DIN + h*64 + p0 + j] = acc[i][j] + Dph*xh;
            }
        }
    }
}

// ---------- y = y*silu(z); rmsnorm * rms_w; pack (x16) ----------
__global__ void k_gaterms(const float* __restrict__ rmsw, unsigned* __restrict__ packout){
    int t = blockIdx.x, tid = threadIdx.x;
    const float* z = &g_zx[(size_t)t*DPJ];
    const float* y = &g_y[(size_t)t*DIN];
    float v[6]; float ss=0.0f;
    #pragma unroll
    for (int j=0;j<6;j++){
        int k = tid + j*256;
        float g = z[k];
        float val = y[k]*siluf(g);
        v[j]=val; ss += val*val;
    }
    __shared__ float red[256];
    red[tid]=ss; __syncthreads();
    for (int o=128;o;o>>=1){ if(tid<o) red[tid]+=red[tid+o]; __syncthreads(); }
    float r = rsqrtf(red[0]*(1.0f/DIN) + 1e-5f);
    unsigned* po = packout + (size_t)t*DIN;
    #pragma unroll
    for (int j=0;j<6;j++){
        int k = tid + j*256;
        po[k] = packh(v[j]*r*rmsw[k]*16.0f);
    }
}

// ---------- residual + image flip ----------
__global__ void k_resid(const float* __restrict__ cur, float* __restrict__ nxt){
    int i = blockIdx.x*256 + threadIdx.x;
    if (i >= TLEN*DM) return;
    int t = i/DM, d = i%DM;
    float hv; int td;
    if (t < 65){ hv = g_mam[i]; td = t; }
    else { int p = t-65; hv = g_img[(size_t)p*DM + d]; td = 65 + (4095-p); }
    nxt[(size_t)td*DM + d] = cur[i] + hv;
}

// ---------- final projection + squared errors ----------
__global__ void k_yhat(const float* __restrict__ x, const float* __restrict__ w,
                       const float* __restrict__ b, const float* __restrict__ im64,
                       float* __restrict__ out, int out_size){
    int p = blockIdx.x;
    int ch = threadIdx.x>>5, lane = threadIdx.x&31;
    const float* xr = x + (size_t)(65+p)*DM;
    float s = 0.0f;
    for (int k=lane;k<DM;k+=32) s += xr[k]*w[ch*DM+k];
    for (int o=16;o;o>>=1) s += __shfl_down_sync(0xffffffffu, s, o);
    if (lane == 0){
        float yh = s + b[ch];
        int idx = p*3 + ch;
        int cap = out_size - (out_size&1);
        if (idx < cap) out[idx] = yh;
        float d = yh - im64[idx];
        g_sq[idx] = d*d;
    }
}
__global__ void k_loss(float* __restrict__ out, int out_size){
    int tid = threadIdx.x;
    float s = 0.0f;
    for (int i=tid;i<12288;i+=256) s += g_sq[i];
    __shared__ float red[256];
    red[tid]=s; __syncthreads();
    for (int o=128;o;o>>=1){ if(tid<o) red[tid]+=red[tid+o]; __syncthreads(); }
    if (tid==0 && (out_size&1)) out[out_size-1] = red[0]*(1.0f/12288.0f);
}

extern "C" void kernel_launch(void* const* d_in, const int* in_sizes, int n_in,
                              void* d_out, int out_size){
    const float* im8       = (const float*)d_in[0];
    const float* im64      = (const float*)d_in[1];
    const float* from_rgbw = (const float*)d_in[2];
    const float* from_rgbb = (const float*)d_in[3];
    const float* to_rgbw   = (const float*)d_in[4];
    const float* to_rgbb   = (const float*)d_in[5];
    const float* s0        = (const float*)d_in[6];
    const float* suffix    = (const float*)d_in[7];
    const float* norm0w    = (const float*)d_in[8];
    const float* norm0b    = (const float*)d_in[9];
    const float* in_projw  = (const float*)d_in[10];
    const float* conv1dw   = (const float*)d_in[11];
    const float* conv1db   = (const float*)d_in[12];
    const float* dt_bias   = (const float*)d_in[13];
    const float* A_log     = (const float*)d_in[14];
    const float* Dp        = (const float*)d_in[15];
    const float* rms_w     = (const float*)d_in[16];
    const float* out_projw = (const float*)d_in[17];
    const float* ln_w      = (const float*)d_in[18];
    const float* ln_b      = (const float*)d_in[19];
    const float* lnc_w     = (const float*)d_in[20];
    const float* lnc_b     = (const float*)d_in[21];
    const float* conv2dw   = (const float*)d_in[22];
    const float* conv2db   = (const float*)d_in[23];

    float *px, *px2, *pmam, *pzx, *pxbc, *pG, *ppart;
    unsigned *ppA, *ppB;
    cudaGetSymbolAddress((void**)&px,   g_x);
    cudaGetSymbolAddress((void**)&px2,  g_x2);
    cudaGetSymbolAddress((void**)&pmam, g_mam);
    cudaGetSymbolAddress((void**)&pzx,  g_zx);
    cudaGetSymbolAddress((void**)&pxbc, g_xBC);
    cudaGetSymbolAddress((void**)&pG,   g_G);
    cudaGetSymbolAddress((void**)&ppart,g_part);
    cudaGetSymbolAddress((void**)&ppA,  g_pA);
    cudaGetSymbolAddress((void**)&ppB,  g_pB);

    const int NB = (TLEN*DM + 255)/256;

    k_e8<<<(64*DM+255)/256, 256>>>(im8, from_rgbw, from_rgbb);
    k_buildx<<<NB, 256>>>(s0, suffix);
    k_ln<<<TLEN, 256>>>(px2, px, norm0w, norm0b);

    float* cur = px; float* nxt = px2;
    for (int i=0;i<8;i++){
        k_ln_pack<<<TLEN, 256>>>(cur, ppA, ln_w + i*DM, ln_b + i*DM);
        k_packw<<<(DPJ*DM+255)/256, 256>>>(in_projw + (size_t)i*DPJ*DM, ppB, DPJ*DM);
        k_mma_nt_h<<<dim3(26,33,1), 256>>>(ppA, DM, ppB, DM,
                                           pzx, DPJ, 0LL, TLEN, DPJ, DM, DM);
        k_dt<<<(TPAD*HH+255)/256, 256>>>(dt_bias + i*HH);
        k_conv1d<<<dim3(13,66), 256>>>(conv1dw + (size_t)i*CVD*4, conv1db + i*CVD);
        k_chunkscan<<<NC*HH, 128>>>(A_log + i*HH);
        k_gemm_nt<<<dim3(2,1,NC), 256>>>(pxbc + 1600, CVD, (long long)128*CVD,
                                         pxbc + 1536, CVD, (long long)128*CVD,
                                         pG, 128, 16384, 128, 128, 64);
        k_states<<<dim3(HH,NC), 256>>>();
        k_state_scan<<<HH, 256>>>();
        k_y<<<dim3(HH,NC), 256>>>(A_log + i*HH, Dp + i*HH);
        k_gaterms<<<TLEN, 256>>>(rms_w + (size_t)i*DIN, ppA);
        k_packw<<<(DM*DIN+255)/256, 256>>>(out_projw + (size_t)i*DM*DIN, ppB, DM*DIN);
        k_mma_nt_h<<<dim3(6,33,2), 256>>>(ppA, DIN, ppB, DIN,
                                          ppart, DM, (long long)TLEN*DM, TLEN, DM, DIN, 768);
        k_red2<<<NB, 256>>>();
        k_ln_pack<<<4096, 256>>>(pmam + (size_t)65*DM, ppA, lnc_w + i*DM, lnc_b + i*DM);
        k_packw<<<(19200*768+255)/256, 256>>>(conv2dw + (size_t)i*14745600, ppB, 19200*768);
        k_conv2d_mma_h<<<dim3(6,32,3), 256>>>(ppB);
        k_red3b<<<(4096*768+255)/256, 256>>>(conv2db + i*DM);
        k_resid<<<NB, 256>>>(cur, nxt);
        float* tmp = cur; cur = nxt; nxt = tmp;
    }
    k_yhat<<<4096, 96>>>(cur, to_rgbw, to_rgbb, im64, (float*)d_out, out_size);
    k_loss<<<1, 256>>>((float*)d_out, out_size);
}